// round 15
// baseline (speedup 1.0000x reference)
#include <cuda_runtime.h>
#include <cuda_fp16.h>
#include <cstdint>

// Problem constants
#define NLUT 59049          // 9^5
#define HW   (1 << 20)      // 1024*1024
#define NPIX (4 * HW)       // B*H*W

// ---------------------------------------------------------------------------
// 64B corner-fused entries, 4 lanes per pixel, 2 pixels per thread.
// Lane id lam = t&3 picks the 16B quarter h[lam]; entries are 64B-aligned so
// the lane quad always sits in ONE 128B line (1 wavefront per gather instr).
//
// P_tab[pos].h[j], j = (c2<<1)|c3  (digits d2,d3 stepped+clamped in-build):
//   x={ch0,ch1}@d4  y={ch2,ch3}@d4  z={ch0,ch1}@d4+1  w={ch2,ch3}@d4+1   (fp16)
//   External corners: c0 (+6561 entries), c1 (+729) -> 4 gathers per lane.
//
// Q_tab[pos].h[j], j = (c0<<1)|c1  (digits d0,d1 stepped+clamped in-build):
//   x={vaa,vba}@d2  y={vab,vbb}@d2  z=..@d2+1  w=..@d2+1
//   (vXY: X = d3 corner, Y = d4 corner).  ONE gather covers all 32 corners.
// ---------------------------------------------------------------------------
struct __align__(64) E64 { uint4 h[4]; };

__device__ E64 P_tab[NLUT];
__device__ E64 Q_tab[NLUT];

static __device__ __forceinline__ uint32_t pack2(float a, float b) {
    __half2 hh = __floats2half2_rn(a, b);
    return *reinterpret_cast<uint32_t*>(&hh);
}

// Merged build: one thread per (pos, j) builds BOTH P_tab[pos].h[j] and
// Q_tab[pos].h[j].
__global__ void build_tables(const float* __restrict__ lut) {
    int t = blockIdx.x * blockDim.x + threadIdx.x;
    if (t >= NLUT * 4) return;
    int j   = t & 3;
    int pos = t >> 2;

    int d4 = pos % 9;
    int d3 = (pos / 9) % 9;
    int d2 = (pos / 81) % 9;
    int d1 = (pos / 729) % 9;
    int d0 = pos / 6561;
    int hi01 = pos / 729;               // d0*9 + d1

    // ---- P quarter: j = (c2<<1)|c3 ----
    {
        int d2h = d2 + (j >> 1); if (d2h > 8) d2h = 8;
        int d3h = d3 + (j & 1);  if (d3h > 8) d3h = 8;
        int sp  = ((hi01 * 9 + d2h) * 9 + d3h) * 9 + d4;
        int spn = (d4 < 8) ? sp + 1 : sp;

        uint4 q;
        q.x = pack2(lut[sp],             lut[NLUT + sp]);
        q.y = pack2(lut[2 * NLUT + sp],  lut[3 * NLUT + sp]);
        q.z = pack2(lut[spn],            lut[NLUT + spn]);
        q.w = pack2(lut[2 * NLUT + spn], lut[3 * NLUT + spn]);
        P_tab[pos].h[j] = q;
    }

    // ---- Q quarter: j = (c0<<1)|c1 ----
    {
        int d0h = d0 + (j >> 1); if (d0h > 8) d0h = 8;
        int d1h = d1 + (j & 1);  if (d1h > 8) d1h = 8;
        int d3p = d3 < 8 ? d3 + 1 : 8;
        int d4p = d4 < 8 ? d4 + 1 : 8;

        const float* c4 = lut + 4 * NLUT;
        int hi  = (d0h * 9 + d1h) * 9 + d2;
        int hip = (d2 < 8) ? hi + 1 : hi;
        int b0  = hi  * 81;
        int b1  = hip * 81;

        uint4 q;
        q.x = pack2(c4[b0 + d3  * 9 + d4 ], c4[b0 + d3p * 9 + d4 ]);
        q.y = pack2(c4[b0 + d3  * 9 + d4p], c4[b0 + d3p * 9 + d4p]);
        q.z = pack2(c4[b1 + d3  * 9 + d4 ], c4[b1 + d3p * 9 + d4 ]);
        q.w = pack2(c4[b1 + d3  * 9 + d4p], c4[b1 + d3p * 9 + d4p]);
        Q_tab[pos].h[j] = q;
    }
}

static __device__ __forceinline__ __half2 u2h(uint32_t v) {
    return *reinterpret_cast<__half2*>(&v);
}

// Per-pixel setup state.
struct Px {
    int   base;
    float w01[4];     // (c0,c1) corner weights
    float w01s[4];    // w01 * this-lane's w23
    float waa, wba, wab, wbb;
    float a2, f2;
    __half2 a4h, f4h, a2h, f2h;
};

static __device__ __forceinline__ void setup_px(const float* __restrict__ xb,
                                                int lam, Px& s) {
    float f[5];
    int   idx[5];
#pragma unroll
    for (int c = 0; c < 5; c++) {
        float v  = __ldg(xb + ((size_t)c << 20)) * 8.0f;
        float fl = floorf(v);                  // x in [0,1) -> fl in [0,7]
        idx[c] = (int)fl;
        f[c]   = v - fl;
    }
    float a0 = 1.0f - f[0], a1 = 1.0f - f[1], a2 = 1.0f - f[2];
    float a3 = 1.0f - f[3], a4 = 1.0f - f[4];

    s.w01[0] = a0 * a1;  s.w01[1] = a0 * f[1];
    s.w01[2] = f[0] * a1; s.w01[3] = f[0] * f[1];

    float w23l = ((lam & 2) ? f[2] : a2) * ((lam & 1) ? f[3] : a3);
#pragma unroll
    for (int m = 0; m < 4; m++) s.w01s[m] = s.w01[m] * w23l;

    s.waa = a3 * a4; s.wba = f[3] * a4; s.wab = a3 * f[4]; s.wbb = f[3] * f[4];
    s.a2 = a2; s.f2 = f[2];
    s.a4h = __float2half2_rn(a4);   s.f4h = __float2half2_rn(f[4]);
    s.a2h = __float2half2_rn(a2);   s.f2h = __float2half2_rn(f[2]);

    s.base = idx[0] * 6561 + idx[1] * 729 + idx[2] * 81 + idx[3] * 9 + idx[4];
}

// 4 lanes per pixel, 2 pixels per thread; fp16 interp + fp16 accumulation
// for channels 0-3, fp32 path for channel 4.
__global__ __launch_bounds__(128, 9)
void pglut_kernel(const float* __restrict__ x, float* __restrict__ out) {
    int t   = blockIdx.x * 128 + threadIdx.x;
    int lam = t & 3;
    int u   = t >> 2;                 // pixel-pair index

    int pixA = 2 * u;                 // global pixel id (pair shares batch b)
    int b = pixA >> 20;
    int p = pixA & (HW - 1);          // even -> p+1 in same plane

    const float* xb = x + ((size_t)b * 5 << 20) + p;

    Px A, B;
    setup_px(xb,     lam, A);
    setup_px(xb + 1, lam, B);

    const uint4* ppA = reinterpret_cast<const uint4*>(P_tab) + A.base * 4 + lam;
    const uint4* ppB = reinterpret_cast<const uint4*>(P_tab) + B.base * 4 + lam;
    const uint4* qpA = reinterpret_cast<const uint4*>(Q_tab) + A.base * 4 + lam;
    const uint4* qpB = reinterpret_cast<const uint4*>(Q_tab) + B.base * 4 + lam;

    // Q gathers first (independent misses in flight behind the P loops).
    uint4 qrA = __ldg(qpA);
    uint4 qrB = __ldg(qpB);

    __half2 z = __float2half2_rn(0.0f);
    __half2 accA01 = z, accA23 = z, accB01 = z, accB23 = z;

    // Channels 0-3: 4 gathers per lane per pixel over (c0,c1). m bits: 2=c0, 1=c1.
#pragma unroll
    for (int m = 0; m < 4; m++) {
        int off4 = (((m & 2) ? 6561 : 0) + ((m & 1) ? 729 : 0)) * 4;
        uint4 rA = __ldg(ppA + off4);
        uint4 rB = __ldg(ppB + off4);

        __half2 WA = __float2half2_rn(A.w01s[m]);
        __half2 tA01 = __hfma2(u2h(rA.z), A.f4h, __hmul2(u2h(rA.x), A.a4h));
        __half2 tA23 = __hfma2(u2h(rA.w), A.f4h, __hmul2(u2h(rA.y), A.a4h));
        accA01 = __hfma2(tA01, WA, accA01);
        accA23 = __hfma2(tA23, WA, accA23);

        __half2 WB = __float2half2_rn(B.w01s[m]);
        __half2 tB01 = __hfma2(u2h(rB.z), B.f4h, __hmul2(u2h(rB.x), B.a4h));
        __half2 tB23 = __hfma2(u2h(rB.w), B.f4h, __hmul2(u2h(rB.y), B.a4h));
        accB01 = __hfma2(tB01, WB, accB01);
        accB23 = __hfma2(tB23, WB, accB23);
    }

    // Channel 4 (fp32 path): lane covers (c0,c1) = lam; d2 interp in fp16.
    float acc4A, acc4B;
    {
        __half2 u0 = __hfma2(u2h(qrA.z), A.f2h, __hmul2(u2h(qrA.x), A.a2h));
        __half2 u1 = __hfma2(u2h(qrA.w), A.f2h, __hmul2(u2h(qrA.y), A.a2h));
        float2 g0 = __half22float2(u0);
        float2 g1 = __half22float2(u1);
        float inner = fmaf(A.waa, g0.x, fmaf(A.wba, g0.y,
                       fmaf(A.wab, g1.x, A.wbb * g1.y)));
        acc4A = A.w01[lam] * inner;
    }
    {
        __half2 u0 = __hfma2(u2h(qrB.z), B.f2h, __hmul2(u2h(qrB.x), B.a2h));
        __half2 u1 = __hfma2(u2h(qrB.w), B.f2h, __hmul2(u2h(qrB.y), B.a2h));
        float2 g0 = __half22float2(u0);
        float2 g1 = __half22float2(u1);
        float inner = fmaf(B.waa, g0.x, fmaf(B.wba, g0.y,
                       fmaf(B.wab, g1.x, B.wbb * g1.y)));
        acc4B = B.w01[lam] * inner;
    }

    // Quad reduction: half2 butterfly for ch0-3, fp32 for ch4.
    accA01 = __hadd2(accA01, __shfl_xor_sync(0xFFFFFFFFu, accA01, 1));
    accA23 = __hadd2(accA23, __shfl_xor_sync(0xFFFFFFFFu, accA23, 1));
    accB01 = __hadd2(accB01, __shfl_xor_sync(0xFFFFFFFFu, accB01, 1));
    accB23 = __hadd2(accB23, __shfl_xor_sync(0xFFFFFFFFu, accB23, 1));
    acc4A += __shfl_xor_sync(0xFFFFFFFFu, acc4A, 1);
    acc4B += __shfl_xor_sync(0xFFFFFFFFu, acc4B, 1);
    accA01 = __hadd2(accA01, __shfl_xor_sync(0xFFFFFFFFu, accA01, 2));
    accA23 = __hadd2(accA23, __shfl_xor_sync(0xFFFFFFFFu, accA23, 2));
    accB01 = __hadd2(accB01, __shfl_xor_sync(0xFFFFFFFFu, accB01, 2));
    accB23 = __hadd2(accB23, __shfl_xor_sync(0xFFFFFFFFu, accB23, 2));
    acc4A += __shfl_xor_sync(0xFFFFFFFFu, acc4A, 2);
    acc4B += __shfl_xor_sync(0xFFFFFFFFu, acc4B, 2);

    if (lam == 0) {
        float2 sA01 = __half22float2(accA01);
        float2 sA23 = __half22float2(accA23);
        float2 sB01 = __half22float2(accB01);
        float2 sB23 = __half22float2(accB23);
        float* ob = out + ((size_t)b * 5 << 20) + p;
        *reinterpret_cast<float2*>(ob)          = make_float2(sA01.x, sB01.x);
        *reinterpret_cast<float2*>(ob + 1 * HW) = make_float2(sA01.y, sB01.y);
        *reinterpret_cast<float2*>(ob + 2 * HW) = make_float2(sA23.x, sB23.x);
        *reinterpret_cast<float2*>(ob + 3 * HW) = make_float2(sA23.y, sB23.y);
        *reinterpret_cast<float2*>(ob + 4 * HW) = make_float2(acc4A, acc4B);
    }
}

extern "C" void kernel_launch(void* const* d_in, const int* in_sizes, int n_in,
                              void* d_out, int out_size) {
    // metadata order: x (4*5*1024*1024), LUT (5*9^5). Guard against swap.
    const float* x   = (const float*)d_in[0];
    const float* lut = (const float*)d_in[1];
    if (n_in >= 2 && in_sizes[0] == 5 * NLUT) {  // inputs swapped
        x   = (const float*)d_in[1];
        lut = (const float*)d_in[0];
    }
    float* out = (float*)d_out;

    build_tables<<<(NLUT * 4 + 255) / 256, 256>>>(lut);
    // 4 lanes/pixel, 2 pixels/thread -> 64 pixels per 128-thread block
    pglut_kernel<<<NPIX / 64, 128>>>(x, out);
}

// round 16
// speedup vs baseline: 1.2484x; 1.2484x over previous
#include <cuda_runtime.h>
#include <cuda_fp16.h>
#include <cstdint>

// Problem constants
#define NLUT 59049          // 9^5
#define HW   (1 << 20)      // 1024*1024
#define NPIX (4 * HW)       // B*H*W

// ---------------------------------------------------------------------------
// 64B corner-fused entries, 4 lanes per pixel, 1 pixel per thread.
// Lane id lam = t&3 picks the 16B quarter h[lam]; entries are 64B-aligned so
// the lane quad always sits in ONE 128B line (1 wavefront per gather instr).
//
// P_tab[pos].h[j], j = (c2<<1)|c3  (digits d2,d3 stepped+clamped in-build):
//   x={ch0,ch1}@d4  y={ch2,ch3}@d4  z={ch0,ch1}@d4+1  w={ch2,ch3}@d4+1   (fp16)
//   External corners: c0 (+6561 entries), c1 (+729) -> 4 gathers per lane.
//
// Q_tab[pos].h[j], j = (c0<<1)|c1  (digits d0,d1 stepped+clamped in-build):
//   x={vaa,vba}@d2  y={vab,vbb}@d2  z=..@d2+1  w=..@d2+1
//   (vXY: X = d3 corner, Y = d4 corner).  ONE gather covers all 32 corners.
// ---------------------------------------------------------------------------
struct __align__(64) E64 { uint4 h[4]; };

__device__ E64 P_tab[NLUT];
__device__ E64 Q_tab[NLUT];

static __device__ __forceinline__ uint32_t pack2(float a, float b) {
    __half2 hh = __floats2half2_rn(a, b);
    return *reinterpret_cast<uint32_t*>(&hh);
}

// Merged build: one thread per (pos, j) builds BOTH P_tab[pos].h[j] and
// Q_tab[pos].h[j].
__global__ void build_tables(const float* __restrict__ lut) {
    int t = blockIdx.x * blockDim.x + threadIdx.x;
    if (t >= NLUT * 4) return;
    int j   = t & 3;
    int pos = t >> 2;

    int d4 = pos % 9;
    int d3 = (pos / 9) % 9;
    int d2 = (pos / 81) % 9;
    int d1 = (pos / 729) % 9;
    int d0 = pos / 6561;
    int hi01 = pos / 729;               // d0*9 + d1

    // ---- P quarter: j = (c2<<1)|c3 ----
    {
        int d2h = d2 + (j >> 1); if (d2h > 8) d2h = 8;
        int d3h = d3 + (j & 1);  if (d3h > 8) d3h = 8;
        int sp  = ((hi01 * 9 + d2h) * 9 + d3h) * 9 + d4;
        int spn = (d4 < 8) ? sp + 1 : sp;

        uint4 q;
        q.x = pack2(lut[sp],             lut[NLUT + sp]);
        q.y = pack2(lut[2 * NLUT + sp],  lut[3 * NLUT + sp]);
        q.z = pack2(lut[spn],            lut[NLUT + spn]);
        q.w = pack2(lut[2 * NLUT + spn], lut[3 * NLUT + spn]);
        P_tab[pos].h[j] = q;
    }

    // ---- Q quarter: j = (c0<<1)|c1 ----
    {
        int d0h = d0 + (j >> 1); if (d0h > 8) d0h = 8;
        int d1h = d1 + (j & 1);  if (d1h > 8) d1h = 8;
        int d3p = d3 < 8 ? d3 + 1 : 8;
        int d4p = d4 < 8 ? d4 + 1 : 8;

        const float* c4 = lut + 4 * NLUT;
        int hi  = (d0h * 9 + d1h) * 9 + d2;
        int hip = (d2 < 8) ? hi + 1 : hi;
        int b0  = hi  * 81;
        int b1  = hip * 81;

        uint4 q;
        q.x = pack2(c4[b0 + d3  * 9 + d4 ], c4[b0 + d3p * 9 + d4 ]);
        q.y = pack2(c4[b0 + d3  * 9 + d4p], c4[b0 + d3p * 9 + d4p]);
        q.z = pack2(c4[b1 + d3  * 9 + d4 ], c4[b1 + d3p * 9 + d4 ]);
        q.w = pack2(c4[b1 + d3  * 9 + d4p], c4[b1 + d3p * 9 + d4p]);
        Q_tab[pos].h[j] = q;
    }
}

static __device__ __forceinline__ __half2 u2h(uint32_t v) {
    return *reinterpret_cast<__half2*>(&v);
}

// 4 lanes per pixel, 1 pixel per thread; fp16 interp + fp16 accumulation
// for channels 0-3, fp32 path for channel 4.
__global__ __launch_bounds__(128, 16)
void pglut_kernel(const float* __restrict__ x, float* __restrict__ out) {
    int t    = blockIdx.x * 128 + threadIdx.x;
    int pix  = t >> 2;
    int lam  = t & 3;

    int b = pix >> 20;
    int p = pix & (HW - 1);

    const float* xb = x + ((size_t)b * 5 << 20) + p;

    float f[5];
    int   idx[5];
#pragma unroll
    for (int c = 0; c < 5; c++) {
        float v  = __ldg(xb + ((size_t)c << 20)) * 8.0f;   // quad lanes: broadcast
        float fl = floorf(v);                               // x in [0,1) -> fl in [0,7]
        idx[c] = (int)fl;
        f[c]   = v - fl;
    }

    float a0 = 1.0f - f[0], a1 = 1.0f - f[1], a2 = 1.0f - f[2];
    float a3 = 1.0f - f[3], a4 = 1.0f - f[4];

    // w01[c0*2 + c1]
    float w01[4] = {a0 * a1, a0 * f[1], f[0] * a1, f[0] * f[1]};

    // P: this lane's (c2, c3) factor  (c2 = lam bit1, c3 = lam bit0)
    float w23l = ((lam & 2) ? f[2] : a2) * ((lam & 1) ? f[3] : a3);

    // Q: (d3,d4) quad weights (same for all lanes)
    float waa = a3 * a4, wba = f[3] * a4, wab = a3 * f[4], wbb = f[3] * f[4];

    // fp16 interp constants
    __half2 a4h = __float2half2_rn(a4), f4h = __float2half2_rn(f[4]);
    __half2 a2h = __float2half2_rn(a2), f2h = __float2half2_rn(f[2]);

    int base = idx[0] * 6561 + idx[1] * 729 + idx[2] * 81 + idx[3] * 9 + idx[4];

    const uint4* pp = reinterpret_cast<const uint4*>(P_tab) + base * 4 + lam;
    const uint4* qp = reinterpret_cast<const uint4*>(Q_tab) + base * 4 + lam;

    // Issue the Q gather first (independent miss in flight behind the P loop).
    uint4 qr = __ldg(qp);

    __half2 z = __float2half2_rn(0.0f);
    __half2 acc01 = z, acc23 = z;
    float acc4;

    // Channels 0-3: 4 gathers per lane over (c0,c1). m bits: 2=c0, 1=c1.
    // d4 interp in fp16, weight in fp16, fp16 accumulation.
#pragma unroll
    for (int m = 0; m < 4; m++) {
        int off4 = (((m & 2) ? 6561 : 0) + ((m & 1) ? 729 : 0)) * 4;
        uint4 r = __ldg(pp + off4);
        __half2 t01 = __hfma2(u2h(r.z), f4h, __hmul2(u2h(r.x), a4h));
        __half2 t23 = __hfma2(u2h(r.w), f4h, __hmul2(u2h(r.y), a4h));
        __half2 W   = __float2half2_rn(w01[m] * w23l);
        acc01 = __hfma2(t01, W, acc01);
        acc23 = __hfma2(t23, W, acc23);
    }

    // Channel 4: consume the prefetched gather. Lane covers (c0,c1);
    // d2 interp in fp16, (d3,d4) quad in fp32.
    {
        __half2 u0 = __hfma2(u2h(qr.z), f2h, __hmul2(u2h(qr.x), a2h));  // (vaa,vba)
        __half2 u1 = __hfma2(u2h(qr.w), f2h, __hmul2(u2h(qr.y), a2h));  // (vab,vbb)
        float2 g0 = __half22float2(u0);
        float2 g1 = __half22float2(u1);
        float inner = fmaf(waa, g0.x, fmaf(wba, g0.y, fmaf(wab, g1.x, wbb * g1.y)));
        acc4 = w01[lam] * inner;     // w01[(c0<<1)|c1]
    }

    // Quad reduction: half2 butterfly for ch0-3 (2 values), fp32 for ch4.
    acc01 = __hadd2(acc01, __shfl_xor_sync(0xFFFFFFFFu, acc01, 1));
    acc23 = __hadd2(acc23, __shfl_xor_sync(0xFFFFFFFFu, acc23, 1));
    acc4 +=            __shfl_xor_sync(0xFFFFFFFFu, acc4,  1);
    acc01 = __hadd2(acc01, __shfl_xor_sync(0xFFFFFFFFu, acc01, 2));
    acc23 = __hadd2(acc23, __shfl_xor_sync(0xFFFFFFFFu, acc23, 2));
    acc4 +=            __shfl_xor_sync(0xFFFFFFFFu, acc4,  2);

    if (lam == 0) {
        float2 s01 = __half22float2(acc01);
        float2 s23 = __half22float2(acc23);
        float* ob = out + ((size_t)b * 5 << 20) + p;
        ob[0]      = s01.x;
        ob[1 * HW] = s01.y;
        ob[2 * HW] = s23.x;
        ob[3 * HW] = s23.y;
        ob[4 * HW] = acc4;
    }
}

extern "C" void kernel_launch(void* const* d_in, const int* in_sizes, int n_in,
                              void* d_out, int out_size) {
    // metadata order: x (4*5*1024*1024), LUT (5*9^5). Guard against swap.
    const float* x   = (const float*)d_in[0];
    const float* lut = (const float*)d_in[1];
    if (n_in >= 2 && in_sizes[0] == 5 * NLUT) {  // inputs swapped
        x   = (const float*)d_in[1];
        lut = (const float*)d_in[0];
    }
    float* out = (float*)d_out;

    build_tables<<<(NLUT * 4 + 255) / 256, 256>>>(lut);
    // 4 lanes per pixel -> 32 pixels per 128-thread block
    pglut_kernel<<<NPIX / 32, 128>>>(x, out);
}